// round 1
// baseline (speedup 1.0000x reference)
#include <cuda_runtime.h>
#include <cuda_bf16.h>

#define NUM_NODES   4000000
#define NUM_PHYS    3000000
#define NUM_MOVABLE 2500000
#define NB          1024
#define NBINS       (NB * NB)

// 4 MB density map scratch (device global: allocation-free per harness rules)
__device__ float g_pmap[NBINS];

__global__ __launch_bounds__(256) void zero_pmap_kernel() {
    int i = blockIdx.x * blockDim.x + threadIdx.x;
    // grid covers NBINS/4 float4 elements
    reinterpret_cast<float4*>(g_pmap)[i] = make_float4(0.f, 0.f, 0.f, 0.f);
}

__global__ __launch_bounds__(256) void scatter_kernel(
    const float* __restrict__ pos,
    const float* __restrict__ nsx,
    const float* __restrict__ nsy,
    const int*   __restrict__ pw)
{
    int i = blockIdx.x * blockDim.x + threadIdx.x;
    if (i >= NUM_PHYS) return;

    float sx = nsx[i];
    float sy = nsy[i];
    float hx = 0.5f * fmaxf(1.414f, sx);   // bsx = 1.0
    float hy = 0.5f * fmaxf(1.414f, sy);
    float cx = pos[i]             + 0.5f * sx;
    float cy = pos[NUM_NODES + i] + 0.5f * sy;
    float xmin = cx - hx, xmax = cx + hx;
    float ymin = cy - hy, ymax = cy + hy;
    float dens = (float)pw[i] / (4.0f * hx * hy);

    int bxl = min(max((int)floorf(xmin), 0), NB - 1);
    int byl = min(max((int)floorf(ymin), 0), NB - 1);

    // Precompute y overlaps for the 4 candidate rows
    float oy[4];
#pragma unroll
    for (int dj = 0; dj < 4; dj++) {
        float byf = (float)(byl + dj);
        oy[dj] = fmaxf(fminf(ymax, byf + 1.0f) - fmaxf(ymin, byf), 0.0f);
    }

#pragma unroll
    for (int di = 0; di < 4; di++) {
        int bx = bxl + di;
        if (bx >= NB) break;
        float bxf = (float)bx;
        float ox = fmaxf(fminf(xmax, bxf + 1.0f) - fmaxf(xmin, bxf), 0.0f);
        if (ox <= 0.0f) continue;           // adding 0 == skipping
        float dox = dens * ox;
        float* row = g_pmap + bx * NB + byl;
#pragma unroll
        for (int dj = 0; dj < 4; dj++) {
            if (byl + dj >= NB) break;
            float v = dox * oy[dj];
            if (v != 0.0f) atomicAdd(row + dj, v);
        }
    }
}

__global__ __launch_bounds__(256) void gather_kernel(
    const float* __restrict__ pos,
    const float* __restrict__ nsx,
    const float* __restrict__ nsy,
    float*       __restrict__ out)
{
    int i = blockIdx.x * blockDim.x + threadIdx.x;
    if (i >= NUM_MOVABLE) return;

    float mx  = pos[i];
    float my  = pos[NUM_NODES + i];
    float msx = nsx[i];
    float msy = nsy[i];
    float xmax = mx + msx;
    float ymax = my + msy;

    int bxl = min(max((int)floorf(mx), 0), NB - 1);
    int byl = min(max((int)floorf(my), 0), NB - 1);

    float oy[4];
#pragma unroll
    for (int dj = 0; dj < 4; dj++) {
        float byf = (float)(byl + dj);
        oy[dj] = fmaxf(fminf(ymax, byf + 1.0f) - fmaxf(my, byf), 0.0f);
    }

    float area = 0.0f;
#pragma unroll
    for (int di = 0; di < 4; di++) {
        int bx = bxl + di;
        if (bx >= NB) break;
        float bxf = (float)bx;
        float ox = fmaxf(fminf(xmax, bxf + 1.0f) - fmaxf(mx, bxf), 0.0f);
        if (ox <= 0.0f) continue;           // term would be 0
        const float* row = g_pmap + bx * NB + byl;
#pragma unroll
        for (int dj = 0; dj < 4; dj++) {
            if (byl + dj >= NB) break;
            float o = ox * oy[dj];
            if (o != 0.0f) {
                // adj = clip(pmap / UNIT_PIN_CAPACITY, 0.4, 2.5); bsx*bsy == 1
                float adj = fminf(fmaxf(row[dj] * 0.5f, 0.4f), 2.5f);
                area += o * adj;
            }
        }
    }
    out[i] = area;
}

extern "C" void kernel_launch(void* const* d_in, const int* in_sizes, int n_in,
                              void* d_out, int out_size)
{
    const float* pos = (const float*)d_in[0];
    const float* nsx = (const float*)d_in[1];
    const float* nsy = (const float*)d_in[2];
    const int*   pw  = (const int*)  d_in[3];
    float* out = (float*)d_out;

    zero_pmap_kernel<<<NBINS / 4 / 256, 256>>>();
    scatter_kernel<<<(NUM_PHYS + 255) / 256, 256>>>(pos, nsx, nsy, pw);
    gather_kernel<<<(NUM_MOVABLE + 255) / 256, 256>>>(pos, nsx, nsy, out);
}